// round 15
// baseline (speedup 1.0000x reference)
#include <cuda_runtime.h>

#define CIN 16
#define DIN 64
#define HIN 96
#define WIN 96
#define DD 32
#define HH 48
#define WW 48
#define NVOX (DD*HH*WW)          /* 73728 */
#define RR 3
#define PD (DD+2*RR)             /* 38 */
#define PH (HH+2*RR)             /* 54 */
#define PW (WW+2*RR)             /* 54 */
#define FMS 64                   /* padded row stride (float4) for g_fm */

#define N_FF (4*NVOX)
#define N_FM (4*PD*PH*PW)
#define NGRP (NVOX/2)            /* 36864 voxel-pairs */

// Pooled features. g_ff: ((z*HH+y)*4+q)*WW + x. g_fm zero-padded by RR each
// side, row stride padded to 64 float4 (aligned rows, shift addressing).
__device__ float4 g_ff[(size_t)DD*HH*4*WW];
__device__ __align__(256) float4 g_fm[(size_t)PD*PH*4*FMS];

// ---------------------------------------------------------------------------
// Fused pooling (both tensors, one grid) + zeroing of the output buffer.
// ---------------------------------------------------------------------------
__global__ void pool_kernel(const float* __restrict__ ff_in,
                            const float* __restrict__ fm_in,
                            float* __restrict__ out) {
    int i = blockIdx.x * blockDim.x + threadIdx.x;
    if (i < 2 * NVOX) out[i] = 0.0f;             // init output (scatter target)
    if (i < N_FF) {
        int x = i % WW;
        int y = (i / WW) % HH;
        int z = (i / (WW * HH)) % DD;
        int q = i / NVOX;
        float s[4];
#pragma unroll
        for (int cc = 0; cc < 4; cc++) {
            int c = q * 4 + cc;
            const float* p = ff_in + (((size_t)c * DIN + 2 * z) * HIN + 2 * y) * WIN + 2 * x;
            float acc = 0.f;
#pragma unroll
            for (int dz = 0; dz < 2; dz++)
#pragma unroll
                for (int dy = 0; dy < 2; dy++) {
                    const float2 v = *(const float2*)(p + (size_t)dz * HIN * WIN + dy * WIN);
                    acc += v.x + v.y;
                }
            s[cc] = acc * 0.125f;
        }
        g_ff[((size_t)(z * HH + y) * 4 + q) * WW + x] = make_float4(s[0], s[1], s[2], s[3]);
    } else {
        int j = i - N_FF;
        if (j >= N_FM) return;
        int x = j % PW;
        int y = (j / PW) % PH;
        int z = (j / (PW * PH)) % PD;
        int q = j / (PD * PH * PW);
        int iz = z - RR, iy = y - RR, ix = x - RR;
        float s[4] = {0.f, 0.f, 0.f, 0.f};
        if (iz >= 0 && iz < DD && iy >= 0 && iy < HH && ix >= 0 && ix < WW) {
#pragma unroll
            for (int cc = 0; cc < 4; cc++) {
                int c = q * 4 + cc;
                const float* p = fm_in + (((size_t)c * DIN + 2 * iz) * HIN + 2 * iy) * WIN + 2 * ix;
                float acc = 0.f;
#pragma unroll
                for (int dz = 0; dz < 2; dz++)
#pragma unroll
                    for (int dy = 0; dy < 2; dy++) {
                        const float2 v = *(const float2*)(p + (size_t)dz * HIN * WIN + dy * WIN);
                        acc += v.x + v.y;
                    }
                s[cc] = acc * 0.125f;
            }
        }
        g_fm[((size_t)(z * PH + y) * 4 + q) * FMS + x] = make_float4(s[0], s[1], s[2], s[3]);
    }
}

// ---------------------------------------------------------------------------
// Shared-memory top-5 list, register threshold. Hot path: compare + rare
// branch. Rare path: load 4 upper entries, cascade (strict > keeps earliest
// p on ties, matching lax.top_k), store back, refresh threshold.
// Semantics identical to the register cascade used since R2.
// ---------------------------------------------------------------------------
__device__ __forceinline__ void smem_ins(float* __restrict__ lv,
                                         int* __restrict__ lp,
                                         float& thr, float c, int p) {
    float v0 = lv[0], v1 = lv[1], v2 = lv[2], v3 = lv[3];
    int   q0 = lp[0], q1 = lp[1], q2 = lp[2], q3 = lp[3];
    float v4 = c;
    int   q4 = p;
    if (v4 > v3) { float f = v4; v4 = v3; v3 = f; int u = q4; q4 = q3; q3 = u; }
    if (v3 > v2) { float f = v3; v3 = v2; v2 = f; int u = q3; q3 = q2; q2 = u; }
    if (v2 > v1) { float f = v2; v2 = v1; v1 = f; int u = q2; q2 = q1; q1 = u; }
    if (v1 > v0) { float f = v1; v1 = v0; v0 = f; int u = q1; q1 = q0; q0 = u; }
    lv[0] = v0; lv[1] = v1; lv[2] = v2; lv[3] = v3; lv[4] = v4;
    lp[0] = q0; lp[1] = q1; lp[2] = q2; lp[3] = q3; lp[4] = q4;
    thr = v4;
}

// ---------------------------------------------------------------------------
// One fm z-slab (7x7 in-plane window) against up to two outputs.
// Channel accumulation sequential c=0..15 (matches reference summation).
// Hot loop per candidate: 4 LDG.128 + 16 FMA + 1 compare (+rare insert).
// ---------------------------------------------------------------------------
template <bool DA, bool DB>
__device__ __forceinline__ void run_slice(
    int zslab, int y, int x, int pA, int pB,
    const float4& A0, const float4& A1, const float4& A2, const float4& A3,
    const float4& B0, const float4& B1, const float4& B2, const float4& B3,
    float* __restrict__ lvA, int* __restrict__ lpA, float& thrA,
    float* __restrict__ lvB, int* __restrict__ lpB, float& thrB)
{
    for (int py = 0; py < 7; py++) {
        const float4* __restrict__ mb =
            &g_fm[((size_t)(zslab * PH + (y + py)) * 4) * FMS + x];
        const int rA = pA + py * 7;
        const int rB = pB + py * 7;
#pragma unroll
        for (int px = 0; px < 7; px++) {
            float4 m0 = mb[px];
            float4 m1 = mb[FMS + px];
            float4 m2 = mb[2 * FMS + px];
            float4 m3 = mb[3 * FMS + px];
            if (DA) {
                float c = A0.x * m0.x;
                c = fmaf(A0.y, m0.y, c); c = fmaf(A0.z, m0.z, c); c = fmaf(A0.w, m0.w, c);
                c = fmaf(A1.x, m1.x, c); c = fmaf(A1.y, m1.y, c);
                c = fmaf(A1.z, m1.z, c); c = fmaf(A1.w, m1.w, c);
                c = fmaf(A2.x, m2.x, c); c = fmaf(A2.y, m2.y, c);
                c = fmaf(A2.z, m2.z, c); c = fmaf(A2.w, m2.w, c);
                c = fmaf(A3.x, m3.x, c); c = fmaf(A3.y, m3.y, c);
                c = fmaf(A3.z, m3.z, c); c = fmaf(A3.w, m3.w, c);
                if (c > thrA) smem_ins(lvA, lpA, thrA, c, rA + px);
            }
            if (DB) {
                float c = B0.x * m0.x;
                c = fmaf(B0.y, m0.y, c); c = fmaf(B0.z, m0.z, c); c = fmaf(B0.w, m0.w, c);
                c = fmaf(B1.x, m1.x, c); c = fmaf(B1.y, m1.y, c);
                c = fmaf(B1.z, m1.z, c); c = fmaf(B1.w, m1.w, c);
                c = fmaf(B2.x, m2.x, c); c = fmaf(B2.y, m2.y, c);
                c = fmaf(B2.z, m2.z, c); c = fmaf(B2.w, m2.w, c);
                c = fmaf(B3.x, m3.x, c); c = fmaf(B3.y, m3.y, c);
                c = fmaf(B3.z, m3.z, c); c = fmaf(B3.w, m3.w, c);
                if (c > thrB) smem_ins(lvB, lpB, thrB, c, rB + px);
            }
        }
    }
}

// ---------------------------------------------------------------------------
// scatter one top-k winner into both output levels
// ---------------------------------------------------------------------------
__device__ __forceinline__ void scatter_one(float* __restrict__ out,
                                            int z, int y, int x,
                                            float v, int pj) {
    const float sc[4] = {1.0f, 0.5f, 0.25f, 0.125f};
    int oz = pj / 49 - 3;
    int oy = (pj / 7) % 7 - 3;
    int ox = pj % 7 - 3;

    // level 0: integer displacement, single unit-weight corner
    {
        int tz = min(max(z + oz, 0), DD - 1);
        int ty = min(max(y + oy, 0), HH - 1);
        int tx = min(max(x + ox, 0), WW - 1);
        atomicAdd(&out[(tz * HH + ty) * WW + tx], v);
    }
    // level 1: displacement * 0.5, trilinear splat
    {
        int fz = oz >> 1, fy = oy >> 1, fx = ox >> 1;   // floor(o/2)
        int ez = oz & 1, ey = oy & 1, ex = ox & 1;      // odd -> two corners
        float wv = v * sc[ez + ey + ex];
        float* out1 = out + NVOX;
#pragma unroll
        for (int cz = 0; cz < 2; cz++) {
            if (cz > ez) break;
            int tz = min(max(z + fz + cz, 0), DD - 1);
#pragma unroll
            for (int cy = 0; cy < 2; cy++) {
                if (cy > ey) break;
                int ty = min(max(y + fy + cy, 0), HH - 1);
#pragma unroll
                for (int cx = 0; cx < 2; cx++) {
                    if (cx > ex) break;
                    int tx = min(max(x + fx + cx, 0), WW - 1);
                    atomicAdd(&out1[(tz * HH + ty) * WW + tx], wv);
                }
            }
        }
    }
}

// merge 4 partial top-5 lists (rows s*32+lane of the smem list arrays, in
// ascending sub order = ascending disjoint p-ranges) -> global top-5.
// Tie-break: equal values -> smaller flat window index p (matches lax.top_k).
__device__ __forceinline__ void merge_scatter_smem(
    const float (*lv)[5], const int (*lp)[5], int lane,
    float* __restrict__ out, int z, int y, int x)
{
    unsigned used = 0;
#pragma unroll
    for (int k = 0; k < 5; k++) {
        float best = -3e38f;
        int bestp = 0x7fffffff;
        int bi = 0;
        for (int s = 0; s < 4; s++) {
            const float* v5 = lv[s * 32 + lane];
            const int*   p5 = lp[s * 32 + lane];
            for (int j = 0; j < 5; j++) {
                int i = s * 5 + j;
                if (used & (1u << i)) continue;
                float v = v5[j];
                int p = p5[j];
                if (v > best || (v == best && p < bestp)) { best = v; bestp = p; bi = i; }
            }
        }
        used |= 1u << bi;
        scatter_one(out, z, y, x, best, bestp);
    }
}

// ---------------------------------------------------------------------------
// Correlation + top-5 + scatter, ZB=2 z-sharing with SMEM top-5 lists.
// A voxel-pair (z, z+1) at (y, x) is handled by the same lane of the block's
// 4 warps; warp w owns fm slabs {2w, 2w+1} of the pair's 8-slab span, so each
// loaded m vector feeds dots for both outputs -> 1.75x fewer L1 bytes per
// output than one-voxel-per-thread (the dominant floor in R9's profile).
// The register cost that killed this design twice (R8: 98 regs -> 13 warps;
// R11: forced cap -> spills) is removed by keeping only the top-5 THRESHOLD
// in a register and the 5-entry lists in shared memory: inserts are rare
// (~15/thread over ~170 candidates), so the hot loop is 4 LDG + 16 FMA +
// 1 compare. Natural register allocation (no min-blocks cap -> no spills).
// Lanes map to 32 consecutive x -> fully coalesced 512B row loads.
// ---------------------------------------------------------------------------
__global__ void __launch_bounds__(128) corr_scatter_kernel(float* __restrict__ out) {
    __shared__ float lvA[128][5], lvB[128][5];
    __shared__ int   lpA[128][5], lpB[128][5];

    const int tid  = threadIdx.x;
    const int lane = tid & 31;
    const int sub  = tid >> 5;                   // 0..3, warp-uniform
    const int grp  = blockIdx.x * 32 + lane;     // exact grid: no guard
    const int x = grp % WW;
    const int y = (grp / WW) % HH;
    const int z = (grp / (WW * HH)) * 2;

    // init own lists (no sync needed: private rows until the final merge)
#pragma unroll
    for (int k = 0; k < 5; k++) {
        lvA[tid][k] = -1e30f; lpA[tid][k] = 0;
        lvB[tid][k] = -1e30f; lpB[tid][k] = 0;
    }
    float thrA = -1e30f, thrB = -1e30f;

    const float4* fa = &g_ff[((size_t)(z * HH + y) * 4) * WW + x];
    float4 A0 = fa[0], A1 = fa[WW], A2 = fa[2 * WW], A3 = fa[3 * WW];
    const float4* fb = &g_ff[((size_t)((z + 1) * HH + y) * 4) * WW + x];
    float4 B0 = fb[0], B1 = fb[WW], B2 = fb[2 * WW], B3 = fb[3 * WW];

    // slab indices for this warp: pza = 2*sub, 2*sub+1 (absolute fm z = z+pza)
    // output A (z): valid for pza <= 6, p = pza*49 + ...
    // output B (z+1): valid for pza >= 1, p = (pza-1)*49 + ...
    {
        const int pza = 2 * sub;
        const int pA = pza * 49, pB = (pza - 1) * 49;
        if (sub == 0)
            run_slice<true, false>(z + pza, y, x, pA, pB, A0, A1, A2, A3,
                                   B0, B1, B2, B3,
                                   lvA[tid], lpA[tid], thrA, lvB[tid], lpB[tid], thrB);
        else
            run_slice<true, true>(z + pza, y, x, pA, pB, A0, A1, A2, A3,
                                  B0, B1, B2, B3,
                                  lvA[tid], lpA[tid], thrA, lvB[tid], lpB[tid], thrB);
    }
    {
        const int pza = 2 * sub + 1;
        const int pA = pza * 49, pB = (pza - 1) * 49;
        if (sub == 3)
            run_slice<false, true>(z + pza, y, x, pA, pB, A0, A1, A2, A3,
                                   B0, B1, B2, B3,
                                   lvA[tid], lpA[tid], thrA, lvB[tid], lpB[tid], thrB);
        else
            run_slice<true, true>(z + pza, y, x, pA, pB, A0, A1, A2, A3,
                                  B0, B1, B2, B3,
                                  lvA[tid], lpA[tid], thrA, lvB[tid], lpB[tid], thrB);
    }

    __syncthreads();

    if (sub == 0) merge_scatter_smem(lvA, lpA, lane, out, z, y, x);
    if (sub == 1) merge_scatter_smem(lvB, lpB, lane, out, z + 1, y, x);
}

// ---------------------------------------------------------------------------
extern "C" void kernel_launch(void* const* d_in, const int* in_sizes, int n_in,
                              void* d_out, int out_size) {
    (void)in_sizes; (void)n_in; (void)out_size;
    const float* feat_fix = (const float*)d_in[0];
    const float* feat_mov = (const float*)d_in[1];
    float* out = (float*)d_out;

    int t = 256;
    int pool_total = N_FF + N_FM;
    pool_kernel<<<(pool_total + t - 1) / t, t>>>(feat_fix, feat_mov, out);

    // 128 threads = 4 warps (2 fm slabs each) x 32 voxel-pairs; NGRP/32 = 1152
    corr_scatter_kernel<<<NGRP / 32, 128>>>(out);
}

// round 17
// speedup vs baseline: 1.4536x; 1.4536x over previous
#include <cuda_runtime.h>

#define CIN 16
#define DIN 64
#define HIN 96
#define WIN 96
#define DD 32
#define HH 48
#define WW 48
#define NVOX (DD*HH*WW)          /* 73728 */
#define RR 3
#define PD (DD+2*RR)             /* 38 */
#define PH (HH+2*RR)             /* 54 */
#define PW (WW+2*RR)             /* 54 */
#define FMS 64                   /* padded row stride (float4) for g_fm */

#define N_FF (4*NVOX)
#define N_FM (4*PD*PH*PW)

// Pooled features. g_ff: ((z*HH+y)*4+q)*WW + x. g_fm zero-padded by RR each
// side, row stride padded to 64 float4 (aligned rows, shift addressing).
__device__ float4 g_ff[(size_t)DD*HH*4*WW];
__device__ __align__(256) float4 g_fm[(size_t)PD*PH*4*FMS];

// ---------------------------------------------------------------------------
// Fused pooling (both tensors, one grid) + zeroing of the output buffer.
// ---------------------------------------------------------------------------
__global__ void pool_kernel(const float* __restrict__ ff_in,
                            const float* __restrict__ fm_in,
                            float* __restrict__ out) {
    int i = blockIdx.x * blockDim.x + threadIdx.x;
    if (i < 2 * NVOX) out[i] = 0.0f;             // init output (scatter target)
    if (i < N_FF) {
        int x = i % WW;
        int y = (i / WW) % HH;
        int z = (i / (WW * HH)) % DD;
        int q = i / NVOX;
        float s[4];
#pragma unroll
        for (int cc = 0; cc < 4; cc++) {
            int c = q * 4 + cc;
            const float* p = ff_in + (((size_t)c * DIN + 2 * z) * HIN + 2 * y) * WIN + 2 * x;
            float acc = 0.f;
#pragma unroll
            for (int dz = 0; dz < 2; dz++)
#pragma unroll
                for (int dy = 0; dy < 2; dy++) {
                    const float2 v = *(const float2*)(p + (size_t)dz * HIN * WIN + dy * WIN);
                    acc += v.x + v.y;
                }
            s[cc] = acc * 0.125f;
        }
        g_ff[((size_t)(z * HH + y) * 4 + q) * WW + x] = make_float4(s[0], s[1], s[2], s[3]);
    } else {
        int j = i - N_FF;
        if (j >= N_FM) return;
        int x = j % PW;
        int y = (j / PW) % PH;
        int z = (j / (PW * PH)) % PD;
        int q = j / (PD * PH * PW);
        int iz = z - RR, iy = y - RR, ix = x - RR;
        float s[4] = {0.f, 0.f, 0.f, 0.f};
        if (iz >= 0 && iz < DD && iy >= 0 && iy < HH && ix >= 0 && ix < WW) {
#pragma unroll
            for (int cc = 0; cc < 4; cc++) {
                int c = q * 4 + cc;
                const float* p = fm_in + (((size_t)c * DIN + 2 * iz) * HIN + 2 * iy) * WIN + 2 * ix;
                float acc = 0.f;
#pragma unroll
                for (int dz = 0; dz < 2; dz++)
#pragma unroll
                    for (int dy = 0; dy < 2; dy++) {
                        const float2 v = *(const float2*)(p + (size_t)dz * HIN * WIN + dy * WIN);
                        acc += v.x + v.y;
                    }
                s[cc] = acc * 0.125f;
            }
        }
        g_fm[((size_t)(z * PH + y) * 4 + q) * FMS + x] = make_float4(s[0], s[1], s[2], s[3]);
    }
}

// ---------------------------------------------------------------------------
// Top-5 insertion (strict > keeps earliest window index on ties -> lax.top_k)
// ---------------------------------------------------------------------------
#define DEF_TOPK(P)                                                           \
    float P##v0 = -1e30f, P##v1 = -1e30f, P##v2 = -1e30f, P##v3 = -1e30f,     \
          P##v4 = -1e30f;                                                     \
    int P##q0 = 0, P##q1 = 0, P##q2 = 0, P##q3 = 0, P##q4 = 0;

#define TOPK_INS(P, cval, pidx)                                               \
    if (cval > P##v4) {                                                       \
        P##v4 = cval; P##q4 = pidx;                                           \
        if (P##v4 > P##v3) { float t = P##v4; P##v4 = P##v3; P##v3 = t;       \
                             int u = P##q4; P##q4 = P##q3; P##q3 = u; }       \
        if (P##v3 > P##v2) { float t = P##v3; P##v3 = P##v2; P##v2 = t;       \
                             int u = P##q3; P##q3 = P##q2; P##q2 = u; }       \
        if (P##v2 > P##v1) { float t = P##v2; P##v2 = P##v1; P##v1 = t;       \
                             int u = P##q2; P##q2 = P##q1; P##q1 = u; }       \
        if (P##v1 > P##v0) { float t = P##v1; P##v1 = P##v0; P##v0 = t;       \
                             int u = P##q1; P##q1 = P##q0; P##q0 = u; }       \
    }

// dot of 16-ch fixed features with moving features, sequential channel order
// (must stay sequential: matches reference summation, rel_err ~9e-8)
__device__ __forceinline__ float dot16(const float4& a0, const float4& a1,
                                       const float4& a2, const float4& a3,
                                       const float4& m0, const float4& m1,
                                       const float4& m2, const float4& m3) {
    float c = a0.x * m0.x;
    c = fmaf(a0.y, m0.y, c); c = fmaf(a0.z, m0.z, c); c = fmaf(a0.w, m0.w, c);
    c = fmaf(a1.x, m1.x, c); c = fmaf(a1.y, m1.y, c);
    c = fmaf(a1.z, m1.z, c); c = fmaf(a1.w, m1.w, c);
    c = fmaf(a2.x, m2.x, c); c = fmaf(a2.y, m2.y, c);
    c = fmaf(a2.z, m2.z, c); c = fmaf(a2.w, m2.w, c);
    c = fmaf(a3.x, m3.x, c); c = fmaf(a3.y, m3.y, c);
    c = fmaf(a3.z, m3.z, c); c = fmaf(a3.w, m3.w, c);
    return c;
}

// ---------------------------------------------------------------------------
// scatter one top-k winner into both output levels
// ---------------------------------------------------------------------------
__device__ __forceinline__ void scatter_one(float* __restrict__ out,
                                            int z, int y, int x,
                                            float v, int pj) {
    const float sc[4] = {1.0f, 0.5f, 0.25f, 0.125f};
    int oz = pj / 49 - 3;
    int oy = (pj / 7) % 7 - 3;
    int ox = pj % 7 - 3;

    // level 0: integer displacement, single unit-weight corner
    {
        int tz = min(max(z + oz, 0), DD - 1);
        int ty = min(max(y + oy, 0), HH - 1);
        int tx = min(max(x + ox, 0), WW - 1);
        atomicAdd(&out[(tz * HH + ty) * WW + tx], v);
    }
    // level 1: displacement * 0.5, trilinear splat
    {
        int fz = oz >> 1, fy = oy >> 1, fx = ox >> 1;   // floor(o/2)
        int ez = oz & 1, ey = oy & 1, ex = ox & 1;      // odd -> two corners
        float wv = v * sc[ez + ey + ex];
        float* out1 = out + NVOX;
#pragma unroll
        for (int cz = 0; cz < 2; cz++) {
            if (cz > ez) break;
            int tz = min(max(z + fz + cz, 0), DD - 1);
#pragma unroll
            for (int cy = 0; cy < 2; cy++) {
                if (cy > ey) break;
                int ty = min(max(y + fy + cy, 0), HH - 1);
#pragma unroll
                for (int cx = 0; cx < 2; cx++) {
                    if (cx > ex) break;
                    int tx = min(max(x + fx + cx, 0), WW - 1);
                    atomicAdd(&out1[(tz * HH + ty) * WW + tx], wv);
                }
            }
        }
    }
}

// merge 2 partial top-5 lists (10 smem entries) -> global top-5, then scatter.
// Tie-break: equal values -> smaller flat window index p (matches lax.top_k;
// partial lists cover disjoint ascending p-ranges so ties resolve by p).
__device__ __forceinline__ void merge_scatter10(const float* __restrict__ sv,
                                                const int* __restrict__ si,
                                                float* __restrict__ out,
                                                int z, int y, int x) {
    unsigned used = 0;
#pragma unroll
    for (int k = 0; k < 5; k++) {
        float best = -3e38f;
        int bestp = 0x7fffffff;
        int bi = 0;
#pragma unroll
        for (int i = 0; i < 10; i++) {
            if (used & (1u << i)) continue;
            float v = sv[i];
            int p = si[i];
            if (v > best || (v == best && p < bestp)) { best = v; bestp = p; bi = i; }
        }
        used |= 1u << bi;
        scatter_one(out, z, y, x, best, bestp);
    }
}

// ---------------------------------------------------------------------------
// Correlation + top-5 + scatter.  R9 skeleton (one voxel per thread, 49
// window rows split 25/24 across a warp-pair, lanes -> 32 consecutive x, so
// each row-q load is a fully coalesced 512B request), with two measured
// adjustments:
//  * 64-THREAD BLOCKS (2 warps = the two window halves of 32 voxels).
//    Halves the per-block register quantum so ~70 regs still keeps ~14
//    blocks (28-29 warps) resident, and improves wave packing (2304 blocks).
//  * CANDIDATE PAIRS: px processed {0,1},{2,3},{4,5},{6}. Each pair is 8
//    branch-free loads + two independent 16-FMA chains, then 2 inserts.
//    MLP 8 / FMA ILP 2 — between R9's fenced MLP-4 (latency-exposed) and
//    R13's MLP-28 (reg bloat + l1tex queue contention, both measured worse).
// Per-candidate FP order and insert order are unchanged (bit-identical).
// ---------------------------------------------------------------------------
__global__ void __launch_bounds__(64) corr_scatter_kernel(float* __restrict__ out) {
    __shared__ float sv[32][10];
    __shared__ int   si[32][10];

    const int lane = threadIdx.x & 31;
    const int half = threadIdx.x >> 5;           // 0/1: which window half
    const int grp  = blockIdx.x * 32 + lane;     // exact grid: no guard
    const int x = grp % WW;
    const int y = (grp / WW) % HH;
    const int z = grp / (WW * HH);

    const float4* fa = &g_ff[((size_t)(z * HH + y) * 4) * WW + x];
    float4 a0 = fa[0], a1 = fa[WW], a2 = fa[2 * WW], a3 = fa[3 * WW];

    DEF_TOPK(A)

    const int r0 = half ? 25 : 0;                // rows 0-24 / 25-48 (175/168)
    const int r1 = half ? 49 : 25;
    for (int r = r0; r < r1; r++) {
        const int pz = r / 7;                    // const-div -> mul/shift
        const int py = r % 7;
        const float4* __restrict__ mb =
            &g_fm[((size_t)((z + pz) * PH + (y + py)) * 4) * FMS + x];
        const int rowp = r * 7;                  // p = pz*49 + py*7 + px

        // candidate pairs: branch-free 8-load + 2-dot block, then 2 inserts
#pragma unroll
        for (int pp = 0; pp < 3; pp++) {
            const int px = 2 * pp;
            float4 m0 = mb[px];
            float4 m1 = mb[FMS + px];
            float4 m2 = mb[2 * FMS + px];
            float4 m3 = mb[3 * FMS + px];
            float4 n0 = mb[px + 1];
            float4 n1 = mb[FMS + px + 1];
            float4 n2 = mb[2 * FMS + px + 1];
            float4 n3 = mb[3 * FMS + px + 1];
            float c1 = dot16(a0, a1, a2, a3, m0, m1, m2, m3);
            float c2 = dot16(a0, a1, a2, a3, n0, n1, n2, n3);
            TOPK_INS(A, c1, rowp + px)
            TOPK_INS(A, c2, rowp + px + 1)
        }
        {   // px = 6 (single)
            float4 m0 = mb[6];
            float4 m1 = mb[FMS + 6];
            float4 m2 = mb[2 * FMS + 6];
            float4 m3 = mb[3 * FMS + 6];
            float c1 = dot16(a0, a1, a2, a3, m0, m1, m2, m3);
            TOPK_INS(A, c1, rowp + 6)
        }
    }

    // publish partial list (disjoint ascending p-ranges across halves)
    float* pv = &sv[lane][half * 5];
    int*   pi = &si[lane][half * 5];
    pv[0] = Av0; pv[1] = Av1; pv[2] = Av2; pv[3] = Av3; pv[4] = Av4;
    pi[0] = Aq0; pi[1] = Aq1; pi[2] = Aq2; pi[3] = Aq3; pi[4] = Aq4;

    __syncthreads();

    if (half == 0)
        merge_scatter10(&sv[lane][0], &si[lane][0], out, z, y, x);
}

// ---------------------------------------------------------------------------
extern "C" void kernel_launch(void* const* d_in, const int* in_sizes, int n_in,
                              void* d_out, int out_size) {
    (void)in_sizes; (void)n_in; (void)out_size;
    const float* feat_fix = (const float*)d_in[0];
    const float* feat_mov = (const float*)d_in[1];
    float* out = (float*)d_out;

    int t = 256;
    int pool_total = N_FF + N_FM;
    pool_kernel<<<(pool_total + t - 1) / t, t>>>(feat_fix, feat_mov, out);

    // 64 threads = 2 warps (window halves) x 32 voxels; NVOX/32 = 2304 blocks
    corr_scatter_kernel<<<NVOX / 32, 64>>>(out);
}